// round 3
// baseline (speedup 1.0000x reference)
#include <cuda_runtime.h>

#define B_ 256
#define S_ 512
#define V_ 32000
#define D_ 100
#define H_ 75
#define HP_ 76
#define L_ 128

// Precomputed emb @ W1^T + b1, padded to stride 76. 32000*76*4 = 9.73 MB (L2-resident).
__device__ float g_embp[V_ * HP_];

// ---------------------------------------------------------------------------
// Kernel 1: embp[v][j] = sum_d emb[v][d] * W1[j][d] + b1[j]
// 500 blocks x 256 threads, 64 emb rows per block.
// ---------------------------------------------------------------------------
__global__ __launch_bounds__(256) void embp_kernel(const float* __restrict__ emb,
                                                   const float* __restrict__ W1,
                                                   const float* __restrict__ b1) {
    __shared__ float w1s[H_ * D_];   // [j][d], row stride 100 floats (conflict-free f4)
    __shared__ float es[64 * D_];    // [rr][d]
    const int r0 = blockIdx.x * 64;

    for (int idx = threadIdx.x; idx < H_ * D_; idx += 256) w1s[idx] = W1[idx];
    for (int idx = threadIdx.x; idx < 64 * D_; idx += 256) es[idx] = emb[r0 * D_ + idx];
    __syncthreads();

    for (int o = threadIdx.x; o < 64 * H_; o += 256) {
        const int rr = o / H_;
        const int j  = o - rr * H_;
        const float* ep = es + rr * D_;
        const float* wp = w1s + j * D_;
        float4 a = {0.f, 0.f, 0.f, 0.f};
#pragma unroll
        for (int k = 0; k < D_ / 4; ++k) {
            float4 ev = *(const float4*)(ep + 4 * k);
            float4 wv = *(const float4*)(wp + 4 * k);
            a.x += ev.x * wv.x; a.y += ev.y * wv.y;
            a.z += ev.z * wv.z; a.w += ev.w * wv.w;
        }
        g_embp[(r0 + rr) * HP_ + j] = a.x + a.y + a.z + a.w + b1[j];
    }
}

// ---------------------------------------------------------------------------
// Kernel 2: persistent recurrence. 128 blocks x 256 threads; block owns 2 rows.
// Phases per step: C (fc of o_{t-1}, pipelined), A (h update), B (o).
// ---------------------------------------------------------------------------
__device__ __forceinline__ float sigmoidf_(float z) {
    return 1.0f / (1.0f + __expf(-z));
}

extern __shared__ float rnn_smem[];

__global__ __launch_bounds__(256, 1) void rnn_kernel(
    const int*   __restrict__ X,
    const float* __restrict__ W2, const float* __restrict__ b2,
    const float* __restrict__ Wo, const float* __restrict__ bo,
    const float* __restrict__ Wfc, const float* __restrict__ bfc,
    float* __restrict__ out)
{
    float* W2s  = rnn_smem;                       // [75][76]
    float* Wos  = rnn_smem + H_ * HP_;            // [75][76]
    float* Wfcs = rnn_smem + 2 * H_ * HP_;        // [128][76]
    float* hs   = Wfcs + L_ * HP_;                // [2][76]
    float* os   = hs + 2 * HP_;                   // [2][76]
    int*   toks = (int*)(os + 2 * HP_);           // [2][512]

    const int tid = threadIdx.x;
    const int b0  = blockIdx.x * 2;

    // ---- init shared state ----
    for (int idx = tid; idx < H_ * H_; idx += 256) {
        int j = idx / H_, k = idx - j * H_;
        W2s[j * HP_ + k] = W2[idx];
        Wos[j * HP_ + k] = Wo[idx];
    }
    for (int idx = tid; idx < L_ * H_; idx += 256) {
        int l = idx / H_, k = idx - l * H_;
        Wfcs[l * HP_ + k] = Wfc[idx];
    }
    if (tid < H_) { W2s[tid * HP_ + H_] = 0.f; Wos[tid * HP_ + H_] = 0.f; }
    if (tid < L_) { Wfcs[tid * HP_ + H_] = 0.f; }
    for (int idx = tid; idx < 2 * HP_; idx += 256) { hs[idx] = 0.f; os[idx] = 0.f; }
    for (int idx = tid; idx < 2 * S_; idx += 256) {
        int i = idx / S_, t = idx - i * S_;
        toks[idx] = X[(b0 + i) * S_ + t];
    }

    const bool rAB = (tid < 2 * H_);
    const int i1 = (tid < H_) ? 0 : 1;
    const int j1 = tid - i1 * H_;                 // only meaningful if rAB
    float b2r = 0.f, bor = 0.f;
    if (rAB) { b2r = b2[j1]; bor = bo[j1]; }

    const int i3 = tid >> 7;                      // 0..1
    const int l3 = tid & 127;                     // 0..127
    const float bfcr = bfc[l3];
    float* outrow = out + ((size_t)(b0 + i3) * S_) * L_ + l3;

    __syncthreads();

    // prefetch xp for t = 0
    float xpv = 0.f;
    if (rAB) xpv = g_embp[toks[i1 * S_ + 0] * HP_ + j1];

    for (int t = 0; t < S_; ++t) {
        // ---- Phase C: fc projection of o_{t-1} (valid for t >= 1) ----
        if (t > 0) {
            const float* op = os + i3 * HP_;
            const float* wp = Wfcs + l3 * HP_;
            float4 a = {0.f, 0.f, 0.f, 0.f};
#pragma unroll
            for (int k = 0; k < HP_ / 4; ++k) {
                float4 ov = *(const float4*)(op + 4 * k);
                float4 wv = *(const float4*)(wp + 4 * k);
                a.x += ov.x * wv.x; a.y += ov.y * wv.y;
                a.z += ov.z * wv.z; a.w += ov.w * wv.w;
            }
            outrow[(size_t)(t - 1) * L_] = a.x + a.y + a.z + a.w + bfcr;
        }

        // ---- Phase A: z = h @ W2^T + xp_t + b2 ----
        float znew = 0.f, xpn = 0.f;
        if (rAB) {
            const float* hp = hs + i1 * HP_;
            const float* wp = W2s + j1 * HP_;
            float4 a = {0.f, 0.f, 0.f, 0.f};
#pragma unroll
            for (int k = 0; k < HP_ / 4; ++k) {
                float4 hv = *(const float4*)(hp + 4 * k);
                float4 wv = *(const float4*)(wp + 4 * k);
                a.x += hv.x * wv.x; a.y += hv.y * wv.y;
                a.z += hv.z * wv.z; a.w += hv.w * wv.w;
            }
            znew = a.x + a.y + a.z + a.w + xpv + b2r;
            if (t + 1 < S_) xpn = g_embp[toks[i1 * S_ + t + 1] * HP_ + j1];
        }
        __syncthreads();   // h reads (A) + o reads (C) complete

        if (rAB) {
            hs[i1 * HP_ + j1] = sigmoidf_(znew);
            xpv = xpn;
        }
        __syncthreads();   // h_new visible

        // ---- Phase B: o = sigmoid(h_new @ Wo^T + bo) ----
        if (rAB) {
            const float* hp = hs + i1 * HP_;
            const float* wp = Wos + j1 * HP_;
            float4 a = {0.f, 0.f, 0.f, 0.f};
#pragma unroll
            for (int k = 0; k < HP_ / 4; ++k) {
                float4 hv = *(const float4*)(hp + 4 * k);
                float4 wv = *(const float4*)(wp + 4 * k);
                a.x += hv.x * wv.x; a.y += hv.y * wv.y;
                a.z += hv.z * wv.z; a.w += hv.w * wv.w;
            }
            os[i1 * HP_ + j1] = sigmoidf_(a.x + a.y + a.z + a.w + bor);
        }
        __syncthreads();   // o_t visible for next iteration's Phase C
    }

    // ---- epilogue: Phase C for t = S-1 ----
    {
        const float* op = os + i3 * HP_;
        const float* wp = Wfcs + l3 * HP_;
        float4 a = {0.f, 0.f, 0.f, 0.f};
#pragma unroll
        for (int k = 0; k < HP_ / 4; ++k) {
            float4 ov = *(const float4*)(op + 4 * k);
            float4 wv = *(const float4*)(wp + 4 * k);
            a.x += ov.x * wv.x; a.y += ov.y * wv.y;
            a.z += ov.z * wv.z; a.w += ov.w * wv.w;
        }
        outrow[(size_t)(S_ - 1) * L_] = a.x + a.y + a.z + a.w + bfcr;
    }
}

// ---------------------------------------------------------------------------
extern "C" void kernel_launch(void* const* d_in, const int* in_sizes, int n_in,
                              void* d_out, int out_size) {
    const int*   X   = (const int*)d_in[0];
    const float* emb = (const float*)d_in[1];
    const float* W1  = (const float*)d_in[2];
    const float* b1  = (const float*)d_in[3];
    const float* W2  = (const float*)d_in[4];
    const float* b2  = (const float*)d_in[5];
    const float* Wo  = (const float*)d_in[6];
    const float* bo  = (const float*)d_in[7];
    const float* Wfc = (const float*)d_in[8];
    const float* bfc = (const float*)d_in[9];
    float* out = (float*)d_out;

    embp_kernel<<<V_ / 64, 256>>>(emb, W1, b1);

    const size_t smem_bytes =
        (size_t)(2 * H_ * HP_ + L_ * HP_ + 4 * HP_) * sizeof(float) + 2 * S_ * sizeof(int);
    cudaFuncSetAttribute(rnn_kernel, cudaFuncAttributeMaxDynamicSharedMemorySize,
                         (int)smem_bytes);
    rnn_kernel<<<B_ / 2, 256, smem_bytes>>>(X, W2, b2, Wo, bo, Wfc, bfc, out);
}

// round 5
// speedup vs baseline: 1.5171x; 1.5171x over previous
#include <cuda_runtime.h>

#define B_ 256
#define S_ 512
#define V_ 32000
#define D_ 100
#define H_ 75
#define HP_ 76   // g_embp row stride
#define KP_ 80   // padded k dimension (4 chunks of 20)
#define L_ 128

// Precomputed emb @ W1^T + b1, stride 76. 32000*76*4 = 9.73 MB (L2-resident).
__device__ float g_embp[V_ * HP_];

// ---------------------------------------------------------------------------
// Kernel 1: embp[v][j] = sum_d emb[v][d] * W1[j][d] + b1[j]
// ---------------------------------------------------------------------------
__global__ __launch_bounds__(256) void embp_kernel(const float* __restrict__ emb,
                                                   const float* __restrict__ W1,
                                                   const float* __restrict__ b1) {
    __shared__ float w1s[H_ * D_];
    __shared__ float es[64 * D_];
    const int r0 = blockIdx.x * 64;

    for (int idx = threadIdx.x; idx < H_ * D_; idx += 256) w1s[idx] = W1[idx];
    for (int idx = threadIdx.x; idx < 64 * D_; idx += 256) es[idx] = emb[r0 * D_ + idx];
    __syncthreads();

    for (int o = threadIdx.x; o < 64 * H_; o += 256) {
        const int rr = o / H_;
        const int j  = o - rr * H_;
        const float* ep = es + rr * D_;
        const float* wp = w1s + j * D_;
        float4 a = {0.f, 0.f, 0.f, 0.f};
#pragma unroll
        for (int k = 0; k < D_ / 4; ++k) {
            float4 ev = *(const float4*)(ep + 4 * k);
            float4 wv = *(const float4*)(wp + 4 * k);
            a.x += ev.x * wv.x; a.y += ev.y * wv.y;
            a.z += ev.z * wv.z; a.w += ev.w * wv.w;
        }
        g_embp[(r0 + rr) * HP_ + j] = a.x + a.y + a.z + a.w + b1[j];
    }
}

// ---------------------------------------------------------------------------
// Packed fp32x2 helpers (sm_103a)
// ---------------------------------------------------------------------------
__device__ __forceinline__ unsigned long long pack2(float lo, float hi) {
    unsigned long long d;
    asm("mov.b64 %0, {%1, %2};" : "=l"(d) : "f"(lo), "f"(hi));
    return d;
}
__device__ __forceinline__ void fma2(unsigned long long& d, unsigned long long a,
                                     unsigned long long b) {
    asm("fma.rn.f32x2 %0, %1, %2, %0;" : "+l"(d) : "l"(a), "l"(b));
}
__device__ __forceinline__ float hsum2(unsigned long long a, unsigned long long b) {
    unsigned long long s;
    asm("add.rn.f32x2 %0, %1, %2;" : "=l"(s) : "l"(a), "l"(b));
    float lo, hi;
    asm("mov.b64 {%0, %1}, %2;" : "=f"(lo), "=f"(hi) : "l"(s));
    return lo + hi;
}
__device__ __forceinline__ float sigm(float z) { return 1.f / (1.f + __expf(-z)); }

// ---------------------------------------------------------------------------
// Kernel 2: persistent-weight recurrence. 128 blocks x 512 threads, 2 rows/block.
// Weights register-resident (packed f32x2). Pipelined: step tt computes
// partials for A(tt) [h-update], B(tt-1) [o], C(tt-2) [fc] from smem state,
// then one reduce phase. 2 barriers/step.
// ---------------------------------------------------------------------------
__global__ __launch_bounds__(512, 1) void rnn_kernel(
    const int*   __restrict__ X,
    const float* __restrict__ W2, const float* __restrict__ b2,
    const float* __restrict__ Wo, const float* __restrict__ bo,
    const float* __restrict__ Wfc, const float* __restrict__ bfc,
    float* __restrict__ out)
{
    __shared__ __align__(16) float hs[2][KP_];   // h state (padded, [75..79]=0)
    __shared__ __align__(16) float os[2][KP_];   // o state
    __shared__ float pA[2][4][KP_];              // partials per k-chunk
    __shared__ float pB[2][4][KP_];
    __shared__ float pC[2][4][L_];
    __shared__ int   toks[2][S_];

    const int tid = threadIdx.x;
    const int b0  = blockIdx.x * 2;

    // A/B producer role: threads 0..299, j = tid%75, chunk q = tid/75
    const bool isAB = tid < 4 * H_;
    const int  ja   = tid % H_;
    const int  qa   = tid / H_;              // 0..3 when isAB
    const int  ka0  = (isAB ? qa : 0) * 20;
    // C producer role: all 512 threads, l = tid&127, chunk qc = tid>>7
    const int  lc   = tid & 127;
    const int  qc   = tid >> 7;
    const int  kc0  = qc * 20;
    // reducer role: threads 0..255, batch row ir, output index rr
    const bool isR  = tid < 256;
    const int  ir   = tid >> 7;              // 0/1
    const int  rr   = tid & 127;

    // ---- init state + tokens ----
    for (int idx = tid; idx < 2 * KP_; idx += 512) {
        ((float*)hs)[idx] = 0.f; ((float*)os)[idx] = 0.f;
    }
    for (int idx = tid; idx < 2 * S_; idx += 512) {
        const int i = idx >> 9, t = idx & (S_ - 1);
        toks[i][t] = X[(b0 + i) * S_ + t];
    }

    // ---- load weights into registers (packed k-pairs) ----
    unsigned long long w2p[10], wop[10], wfp[10];
#pragma unroll
    for (int c = 0; c < 10; ++c) {
        const int k = ka0 + 2 * c;
        float lo = 0.f, hi = 0.f;
        if (isAB) {
            if (k     < H_) lo = W2[ja * H_ + k];
            if (k + 1 < H_) hi = W2[ja * H_ + k + 1];
        }
        w2p[c] = pack2(lo, hi);
        lo = 0.f; hi = 0.f;
        if (isAB) {
            if (k     < H_) lo = Wo[ja * H_ + k];
            if (k + 1 < H_) hi = Wo[ja * H_ + k + 1];
        }
        wop[c] = pack2(lo, hi);
        const int kc = kc0 + 2 * c;
        lo = 0.f; hi = 0.f;
        if (kc     < H_) lo = Wfc[lc * H_ + kc];
        if (kc + 1 < H_) hi = Wfc[lc * H_ + kc + 1];
        wfp[c] = pack2(lo, hi);
    }

    float b2r = 0.f, bor = 0.f, bfcr = 0.f;
    if (isR) {
        if (rr < H_) { b2r = b2[rr]; bor = bo[rr]; }
        bfcr = bfc[rr];
    }
    float* outp = out + ((size_t)(b0 + ir) * S_) * L_ + rr;

    __syncthreads();

    float xpv = 0.f;
    if (isR && rr < H_) xpv = g_embp[(size_t)toks[ir][0] * HP_ + rr];

    // ---- main loop: tt = 0 .. S+1 (pipelined epilogue) ----
    for (int tt = 0; tt < S_ + 2; ++tt) {
        const bool doA = tt < S_;
        const bool doB = (tt >= 1) && (tt <= S_);
        const bool doC = tt >= 2;

        // --- partial phase ---
        if (doC) {
#pragma unroll
            for (int i = 0; i < 2; ++i) {
                const ulonglong2* op = (const ulonglong2*)&os[i][kc0];
                unsigned long long a0 = 0ull, a1 = 0ull;
#pragma unroll
                for (int c = 0; c < 5; ++c) {
                    const ulonglong2 ov = op[c];      // broadcast LDS.128
                    fma2(a0, wfp[2 * c],     ov.x);
                    fma2(a1, wfp[2 * c + 1], ov.y);
                }
                pC[i][qc][lc] = hsum2(a0, a1);
            }
        }
        if (isAB && (doA || doB)) {
#pragma unroll
            for (int i = 0; i < 2; ++i) {
                const ulonglong2* hp = (const ulonglong2*)&hs[i][ka0];
                unsigned long long a0 = 0ull, a1 = 0ull, c0 = 0ull, c1 = 0ull;
#pragma unroll
                for (int c = 0; c < 5; ++c) {
                    const ulonglong2 hv = hp[c];      // broadcast LDS.128, shared by A & B
                    fma2(a0, w2p[2 * c],     hv.x);
                    fma2(c0, wop[2 * c],     hv.x);
                    fma2(a1, w2p[2 * c + 1], hv.y);
                    fma2(c1, wop[2 * c + 1], hv.y);
                }
                pA[i][qa][ja] = hsum2(a0, a1);
                pB[i][qa][ja] = hsum2(c0, c1);
            }
        }
        __syncthreads();

        // --- reduce phase ---
        if (isR) {
            if (doB && rr < H_) {
                const float z = pB[ir][0][rr] + pB[ir][1][rr]
                              + pB[ir][2][rr] + pB[ir][3][rr] + bor;
                os[ir][rr] = sigm(z);                 // o_{tt-1}
            }
            if (doA && rr < H_) {
                const float z = pA[ir][0][rr] + pA[ir][1][rr]
                              + pA[ir][2][rr] + pA[ir][3][rr] + xpv + b2r;
                hs[ir][rr] = sigm(z);                 // h_tt
                if (tt + 1 < S_)
                    xpv = g_embp[(size_t)toks[ir][tt + 1] * HP_ + rr];
            }
            if (doC) {
                const float v = pC[ir][0][rr] + pC[ir][1][rr]
                              + pC[ir][2][rr] + pC[ir][3][rr] + bfcr;
                outp[(size_t)(tt - 2) * L_] = v;      // out_{tt-2}
            }
        }
        __syncthreads();
    }
}

// ---------------------------------------------------------------------------
extern "C" void kernel_launch(void* const* d_in, const int* in_sizes, int n_in,
                              void* d_out, int out_size) {
    const int*   X   = (const int*)d_in[0];
    const float* emb = (const float*)d_in[1];
    const float* W1  = (const float*)d_in[2];
    const float* b1  = (const float*)d_in[3];
    const float* W2  = (const float*)d_in[4];
    const float* b2  = (const float*)d_in[5];
    const float* Wo  = (const float*)d_in[6];
    const float* bo  = (const float*)d_in[7];
    const float* Wfc = (const float*)d_in[8];
    const float* bfc = (const float*)d_in[9];
    float* out = (float*)d_out;

    embp_kernel<<<V_ / 64, 256>>>(emb, W1, b1);
    rnn_kernel<<<B_ / 2, 512>>>(X, W2, b2, Wo, bo, Wfc, bfc, out);
}